// round 7
// baseline (speedup 1.0000x reference)
#include <cuda_runtime.h>
#include <cuda_bf16.h>

#define EPS 1e-6f
#define NB 16
#define NA 10
#define NT 30
#define NP_POLY 16
#define NV 200
#define SEGP (NV - 1)            // 199 segments per polygon
#define NPTS_WARP 8
#define WARPS 4
#define THREADS (WARPS * 32)     // 128
#define NBA (NB * NA)            // 160
#define GRID (NBA * NP_POLY)     // 2560
#define NSLOT (NBA * NT)         // 4800

// cross-poly folded partials, zero-init (valid for ~bits atomicMax), reset by finisher
__device__ unsigned g_md[NSLOT];   // max of ~bits(d2) == min d2
__device__ int      g_ct[NSLOT];   // crossing counts

__device__ __forceinline__ unsigned warp_redux_min_u32(unsigned v) {
    unsigned r;
    asm("redux.sync.min.u32 %0, %1, 0xffffffff;" : "=r"(r) : "r"(v));
    return r;
}
__device__ __forceinline__ int warp_redux_add_s32(int v) {
    int r;
    asm("redux.sync.add.s32 %0, %1, 0xffffffff;" : "=r"(r) : "r"(v));
    return r;
}

__global__ __launch_bounds__(THREADS)
void offroad_main_kernel(const float* __restrict__ points,
                         const float* __restrict__ polys) {
    __shared__ float4 s4[SEGP];   // {sx, sy, ex, ey}
    __shared__ float2 s2[SEGP];   // {1/(esq+eps), 1/(slope+eps)}

    int bx = blockIdx.x;
    int p  = bx & (NP_POLY - 1);
    int ba = bx >> 4;             // b*NA + a
    int b  = ba / NA;
    int tid = threadIdx.x;

    // ---- in-block segment precompute (exact IEEE divs, matches reference) ----
    const float2* pv = (const float2*)polys + ((size_t)(b * NP_POLY + p)) * NV;
    for (int i = tid; i < SEGP; i += THREADS) {
        float2 v0 = pv[i];
        float2 v1 = pv[i + 1];
        float evx = v1.x - v0.x;
        float evy = v1.y - v0.y;
        float esq = fmaf(evx, evx, evy * evy);
        float rcp_esq = 1.0f / (esq + EPS);
        float slope   = evy / (evx + EPS);
        float rcp_sl  = 1.0f / (slope + EPS);
        s4[i] = make_float4(v0.x, v0.y, v1.x, v1.y);
        s2[i] = make_float2(rcp_esq, rcp_sl);
    }
    __syncthreads();

    // ---- sweep (R2-proven geometry: 4 warps x 8 points, lane-strided segs) ----
    int wid = tid >> 5;
    int ln  = tid & 31;
    int t0  = wid * NPTS_WARP;

    float px[NPTS_WARP], py[NPTS_WARP], md[NPTS_WARP];
    int   ct[NPTS_WARP];

    const float2* pts2 = (const float2*)points;
#pragma unroll
    for (int k = 0; k < NPTS_WARP; k++) {
        int t = t0 + k;
        float2 pt = (t < NT) ? pts2[ba * NT + t] : make_float2(1e30f, 1e30f);
        px[k] = pt.x; py[k] = pt.y;
        md[k] = 3.4e38f;
        ct[k] = 0;
    }

#pragma unroll 1
    for (int s = ln; s < SEGP; s += 32) {
        float4 sg = s4[s];
        float2 rr = s2[s];
        float evx = sg.z - sg.x;
        float evy = sg.w - sg.y;
#pragma unroll
        for (int k = 0; k < NPTS_WARP; k++) {
            float v1x = px[k] - sg.x;
            float v1y = py[k] - sg.y;
            float dot = fmaf(v1x, evx, v1y * evy);
            float proj = __saturatef(dot * rr.x);
            float dx = fmaf(-evx, proj, v1x);
            float dy = fmaf(-evy, proj, v1y);
            float d2 = fmaf(dx, dx, dy * dy);
            md[k] = fminf(md[k], d2);
            bool c1 = (sg.y <= py[k]);
            bool c2 = (sg.w <= py[k]);
            float ix = fmaf(v1y, rr.y, sg.x);
            ct[k] += ((c1 != c2) & (ix > px[k])) ? 1 : 0;
        }
    }

    // ---- warp fold (redux) + cross-block fold (L2 atomics, order-independent) ----
#pragma unroll
    for (int k = 0; k < NPTS_WARP; k++) {
        unsigned mb = warp_redux_min_u32(__float_as_uint(md[k]));  // d2 >= 0: bit-monotone
        int      cc = warp_redux_add_s32(ct[k]);
        int t = t0 + k;
        if (ln == 0 && t < NT) {
            int idx = ba * NT + t;
            atomicMax(&g_md[idx], ~mb);
            if (cc) atomicAdd(&g_ct[idx], cc);
        }
    }
}

__global__ __launch_bounds__(32)
void finish_kernel(float* __restrict__ out) {
    int ba = blockIdx.x;      // 0..159
    int t  = threadIdx.x;     // 0..31
    int idx = ba * NT + t;

    float loss = 0.0f;
    unsigned mraw = 0u;
    if (t < NT) {
        mraw = g_md[idx];
        int cc = g_ct[idx];
        float m = __uint_as_float(~mraw);
        float d = sqrtf(fmaxf(m, EPS));
        if (cc & 1) d = -d;
        loss = fmaxf(d + 0.5f, 0.0f);
        // reset this block's own slots for the next graph replay
        g_md[idx] = 0u;
        g_ct[idx] = 0;
    }
    // deterministic fixed-tree sum over t
#pragma unroll
    for (int o = 16; o > 0; o >>= 1)
        loss += __shfl_xor_sync(0xffffffffu, loss, o);
    if (t == 0) out[ba] = loss;
}

extern "C" void kernel_launch(void* const* d_in, const int* in_sizes, int n_in,
                              void* d_out, int out_size) {
    const float* points = (const float*)d_in[0];  // (16,10,30,2)
    const float* polys  = (const float*)d_in[1];  // (16,16,200,2)
    float* out = (float*)d_out;                   // (16,10)

    offroad_main_kernel<<<GRID, THREADS>>>(points, polys);
    finish_kernel<<<NBA, 32>>>(out);
}

// round 8
// speedup vs baseline: 1.3653x; 1.3653x over previous
#include <cuda_runtime.h>
#include <cuda_bf16.h>

#define EPS 1e-6f
#define NB 16
#define NA 10
#define NT 30
#define NP_POLY 16
#define NV 200
#define SEG_PER_POLY (NV - 1)            // 199
#define NSEG (NP_POLY * SEG_PER_POLY)    // 3184 per batch
#define NPTS_WARP 10
#define WARPS 3
#define THREADS (WARPS * 32)             // 96: 3 warps x 10 pts = 30 = NT exactly
#define NBA (NB * NA)                    // 160
#define GRID (NBA * NP_POLY)             // 2560

// per-(batch,segment) precomputed tables
__device__ float4 g_segA[NB * NSEG];  // {sx, sy, evx, evy}
__device__ float4 g_segB[NB * NSEG];  // {ey, 1/(esq+eps), 1/(slope+eps), 0}

// partial results: [ (b*NA+a)*NT + t ][ poly ]  (poly contiguous)
__device__ float g_md[NBA * NT * NP_POLY];
__device__ int   g_ct[NBA * NT * NP_POLY];

__global__ void precompute_kernel(const float* __restrict__ polys) {
    int idx = blockIdx.x * blockDim.x + threadIdx.x;
    if (idx >= NB * NSEG) return;
    int b = idx / NSEG;
    int s = idx - b * NSEG;
    int p = s / SEG_PER_POLY;
    int j = s - p * SEG_PER_POLY;
    const float* v = polys + (((size_t)b * NP_POLY + p) * NV + j) * 2;
    float sx = v[0], sy = v[1], ex = v[2], ey = v[3];
    float evx = ex - sx;                    // same IEEE subs as reference
    float evy = ey - sy;
    float esq = fmaf(evx, evx, evy * evy);
    float rcp_esq = 1.0f / (esq + EPS);
    float slope = evy / (evx + EPS);
    float rcp_sl = 1.0f / (slope + EPS);
    g_segA[idx] = make_float4(sx, sy, evx, evy);
    g_segB[idx] = make_float4(ey, rcp_esq, rcp_sl, 0.0f);
}

__global__ __launch_bounds__(THREADS)
void offroad_main_kernel(const float* __restrict__ points) {
    // block = ((b*NA + a) * NP_POLY + p)
    int bx = blockIdx.x;
    int p  = bx & (NP_POLY - 1);
    int ba = bx >> 4;                    // b*NA + a
    int b  = ba / NA;

    int wid = threadIdx.x >> 5;
    int ln  = threadIdx.x & 31;
    int t0  = wid * NPTS_WARP;           // 0,10,20 -> all t valid

    float px[NPTS_WARP], py[NPTS_WARP], md[NPTS_WARP];
    int   ct[NPTS_WARP];

    const float2* pts2 = (const float2*)points;
#pragma unroll
    for (int k = 0; k < NPTS_WARP; k++) {
        float2 pt = pts2[ba * NT + t0 + k];
        px[k] = pt.x; py[k] = pt.y;
        md[k] = 3.4e38f;
        ct[k] = 0;
    }

    const float4* sA = g_segA + (b * NSEG + p * SEG_PER_POLY);
    const float4* sB = g_segB + (b * NSEG + p * SEG_PER_POLY);

#pragma unroll 1
    for (int s = ln; s < SEG_PER_POLY; s += 32) {
        float4 a = __ldg(&sA[s]);        // {sx, sy, evx, evy}
        float4 q = __ldg(&sB[s]);        // {ey, rcp_esq, rcp_sl, -}
#pragma unroll
        for (int k = 0; k < NPTS_WARP; k++) {
            float v1x = px[k] - a.x;
            float v1y = py[k] - a.y;
            float dot = fmaf(v1x, a.z, v1y * a.w);
            float proj = __saturatef(dot * q.y);
            float dx = fmaf(-a.z, proj, v1x);
            float dy = fmaf(-a.w, proj, v1y);
            float d2 = fmaf(dx, dx, dy * dy);
            md[k] = fminf(md[k], d2);
            // cond_y == (sy<=py) XOR (ey<=py)
            bool c1 = (a.y <= py[k]);
            bool c2 = (q.x <= py[k]);
            float ix = fmaf(v1y, q.z, a.x);   // sx + (py-sy)*rcp_slope
            ct[k] += ((c1 != c2) & (ix > px[k])) ? 1 : 0;
        }
    }

    // warp reduction (champion's butterfly)
#pragma unroll
    for (int k = 0; k < NPTS_WARP; k++) {
#pragma unroll
        for (int o = 16; o > 0; o >>= 1) {
            md[k] = fminf(md[k], __shfl_xor_sync(0xffffffffu, md[k], o));
            ct[k] += __shfl_xor_sync(0xffffffffu, ct[k], o);
        }
    }

    if (ln == 0) {
#pragma unroll
        for (int k = 0; k < NPTS_WARP; k++) {
            int idx = (ba * NT + t0 + k) * NP_POLY + p;
            g_md[idx] = md[k];
            g_ct[idx] = ct[k];
        }
    }
}

__global__ __launch_bounds__(32)
void reduce_kernel(float* __restrict__ out) {
    int ba = blockIdx.x;   // 0..159
    int t  = threadIdx.x;  // 0..31
    float loss = 0.0f;
    if (t < NT) {
        float md = 3.4e38f;
        int ct = 0;
        const float4* pm = (const float4*)(g_md + (ba * NT + t) * NP_POLY);
        const int4*   pc = (const int4*)  (g_ct + (ba * NT + t) * NP_POLY);
#pragma unroll
        for (int q = 0; q < NP_POLY / 4; q++) {
            float4 mv = pm[q];
            int4   cv = pc[q];
            md = fminf(md, fminf(fminf(mv.x, mv.y), fminf(mv.z, mv.w)));
            ct += cv.x + cv.y + cv.z + cv.w;
        }
        float d = sqrtf(fmaxf(md, EPS));
        if (ct & 1) d = -d;
        loss = fmaxf(d + 0.5f, 0.0f);
    }
    // deterministic fixed-tree sum over t
#pragma unroll
    for (int o = 16; o > 0; o >>= 1)
        loss += __shfl_xor_sync(0xffffffffu, loss, o);
    if (t == 0) out[ba] = loss;
}

extern "C" void kernel_launch(void* const* d_in, const int* in_sizes, int n_in,
                              void* d_out, int out_size) {
    const float* points = (const float*)d_in[0];  // (16,10,30,2)
    const float* polys  = (const float*)d_in[1];  // (16,16,200,2)
    float* out = (float*)d_out;                   // (16,10)

    int total = NB * NSEG;
    precompute_kernel<<<(total + 255) / 256, 256>>>(polys);
    offroad_main_kernel<<<GRID, THREADS>>>(points);
    reduce_kernel<<<NBA, 32>>>(out);
}

// round 9
// speedup vs baseline: 1.3672x; 1.0014x over previous
#include <cuda_runtime.h>
#include <cuda_bf16.h>

#define EPS 1e-6f
#define NB 16
#define NA 10
#define NT 30
#define NP_POLY 16
#define NV 200
#define SEG_PER_POLY (NV - 1)            // 199
#define NSEG (NP_POLY * SEG_PER_POLY)    // 3184 per batch
#define NPTS_WARP 10
#define WARPS 3
#define THREADS (WARPS * 32)             // 96: 3 warps x 10 pts = 30 = NT exactly
#define NBA (NB * NA)                    // 160
#define GRID (NBA * NP_POLY)             // 2560

// per-(batch,segment) precomputed tables
__device__ float4 g_segA[NB * NSEG];  // {sx, sy, evx, evy}
__device__ float4 g_segB[NB * NSEG];  // {ey, 1/(esq+eps), 1/(slope+eps), 0}

// partial results: [ (b*NA+a)*NT + t ][ poly ]  (poly contiguous)
__device__ float g_md[NBA * NT * NP_POLY];
__device__ int   g_ct[NBA * NT * NP_POLY];

__device__ __forceinline__ void pdl_wait() {
    asm volatile("griddepcontrol.wait;" ::: "memory");
}
__device__ __forceinline__ void pdl_trigger() {
    asm volatile("griddepcontrol.launch_dependents;" ::: "memory");
}

__global__ void precompute_kernel(const float* __restrict__ polys) {
    int idx = blockIdx.x * blockDim.x + threadIdx.x;
    if (idx >= NB * NSEG) return;
    int b = idx / NSEG;
    int s = idx - b * NSEG;
    int p = s / SEG_PER_POLY;
    int j = s - p * SEG_PER_POLY;
    const float* v = polys + (((size_t)b * NP_POLY + p) * NV + j) * 2;
    float sx = v[0], sy = v[1], ex = v[2], ey = v[3];
    float evx = ex - sx;                    // same IEEE subs as reference
    float evy = ey - sy;
    float esq = fmaf(evx, evx, evy * evy);
    float rcp_esq = 1.0f / (esq + EPS);
    float slope = evy / (evx + EPS);
    float rcp_sl = 1.0f / (slope + EPS);
    g_segA[idx] = make_float4(sx, sy, evx, evy);
    g_segB[idx] = make_float4(ey, rcp_esq, rcp_sl, 0.0f);
}

__global__ __launch_bounds__(THREADS)
void offroad_main_kernel(const float* __restrict__ points) {
    // block = ((b*NA + a) * NP_POLY + p)
    int bx = blockIdx.x;
    int p  = bx & (NP_POLY - 1);
    int ba = bx >> 4;                    // b*NA + a
    int b  = ba / NA;

    int wid = threadIdx.x >> 5;
    int ln  = threadIdx.x & 31;
    int t0  = wid * NPTS_WARP;           // 0,10,20 -> all t valid

    float px[NPTS_WARP], py[NPTS_WARP], md[NPTS_WARP];
    int   ct[NPTS_WARP];

    // points do NOT depend on precompute -> load before the PDL wait
    const float2* pts2 = (const float2*)points;
#pragma unroll
    for (int k = 0; k < NPTS_WARP; k++) {
        float2 pt = pts2[ba * NT + t0 + k];
        px[k] = pt.x; py[k] = pt.y;
        md[k] = 3.4e38f;
        ct[k] = 0;
    }

    // gate only the table reads on precompute completion
    pdl_wait();

    const float4* sA = g_segA + (b * NSEG + p * SEG_PER_POLY);
    const float4* sB = g_segB + (b * NSEG + p * SEG_PER_POLY);

#pragma unroll 1
    for (int s = ln; s < SEG_PER_POLY; s += 32) {
        float4 a = __ldg(&sA[s]);        // {sx, sy, evx, evy}
        float4 q = __ldg(&sB[s]);        // {ey, rcp_esq, rcp_sl, -}
#pragma unroll
        for (int k = 0; k < NPTS_WARP; k++) {
            float v1x = px[k] - a.x;
            float v1y = py[k] - a.y;
            float dot = fmaf(v1x, a.z, v1y * a.w);
            float proj = __saturatef(dot * q.y);
            float dx = fmaf(-a.z, proj, v1x);
            float dy = fmaf(-a.w, proj, v1y);
            float d2 = fmaf(dx, dx, dy * dy);
            md[k] = fminf(md[k], d2);
            // cond_y == (sy<=py) XOR (ey<=py)
            bool c1 = (a.y <= py[k]);
            bool c2 = (q.x <= py[k]);
            float ix = fmaf(v1y, q.z, a.x);   // sx + (py-sy)*rcp_slope
            ct[k] += ((c1 != c2) & (ix > px[k])) ? 1 : 0;
        }
    }

    // warp reduction (champion's butterfly)
#pragma unroll
    for (int k = 0; k < NPTS_WARP; k++) {
#pragma unroll
        for (int o = 16; o > 0; o >>= 1) {
            md[k] = fminf(md[k], __shfl_xor_sync(0xffffffffu, md[k], o));
            ct[k] += __shfl_xor_sync(0xffffffffu, ct[k], o);
        }
    }

    if (ln == 0) {
#pragma unroll
        for (int k = 0; k < NPTS_WARP; k++) {
            int idx = (ba * NT + t0 + k) * NP_POLY + p;
            g_md[idx] = md[k];
            g_ct[idx] = ct[k];
        }
    }

    // signal dependents once this CTA's stores are done
    __syncthreads();
    pdl_trigger();
}

__global__ __launch_bounds__(32)
void reduce_kernel(float* __restrict__ out) {
    int ba = blockIdx.x;   // 0..159
    int t  = threadIdx.x;  // 0..31

    pdl_wait();            // wait until main's CTAs have all triggered

    float loss = 0.0f;
    if (t < NT) {
        float md = 3.4e38f;
        int ct = 0;
        const float4* pm = (const float4*)(g_md + (ba * NT + t) * NP_POLY);
        const int4*   pc = (const int4*)  (g_ct + (ba * NT + t) * NP_POLY);
#pragma unroll
        for (int q = 0; q < NP_POLY / 4; q++) {
            float4 mv = pm[q];
            int4   cv = pc[q];
            md = fminf(md, fminf(fminf(mv.x, mv.y), fminf(mv.z, mv.w)));
            ct += cv.x + cv.y + cv.z + cv.w;
        }
        float d = sqrtf(fmaxf(md, EPS));
        if (ct & 1) d = -d;
        loss = fmaxf(d + 0.5f, 0.0f);
    }
    // deterministic fixed-tree sum over t
#pragma unroll
    for (int o = 16; o > 0; o >>= 1)
        loss += __shfl_xor_sync(0xffffffffu, loss, o);
    if (t == 0) out[ba] = loss;
}

extern "C" void kernel_launch(void* const* d_in, const int* in_sizes, int n_in,
                              void* d_out, int out_size) {
    const float* points = (const float*)d_in[0];  // (16,10,30,2)
    const float* polys  = (const float*)d_in[1];  // (16,16,200,2)
    float* out = (float*)d_out;                   // (16,10)

    // kernel 1: plain launch
    int total = NB * NSEG;
    precompute_kernel<<<(total + 255) / 256, 256>>>(polys);

    // kernels 2 & 3: programmatic dependent launches (overlap with producer)
    cudaLaunchAttribute attr[1];
    attr[0].id = cudaLaunchAttributeProgrammaticStreamSerialization;
    attr[0].val.programmaticStreamSerializationAllowed = 1;

    cudaLaunchConfig_t cfg_main = {};
    cfg_main.gridDim  = dim3(GRID, 1, 1);
    cfg_main.blockDim = dim3(THREADS, 1, 1);
    cfg_main.attrs = attr;
    cfg_main.numAttrs = 1;
    cudaLaunchKernelEx(&cfg_main, offroad_main_kernel, points);

    cudaLaunchConfig_t cfg_red = {};
    cfg_red.gridDim  = dim3(NBA, 1, 1);
    cfg_red.blockDim = dim3(32, 1, 1);
    cfg_red.attrs = attr;
    cfg_red.numAttrs = 1;
    cudaLaunchKernelEx(&cfg_red, reduce_kernel, out);
}